// round 4
// baseline (speedup 1.0000x reference)
#include <cuda_runtime.h>

#define NN  400
#define FF  240
#define CC  32
#define LL  1440

// ---------------- scratch (device globals; no allocation allowed) ----------------
__device__ __align__(16) float g_U[NN*CC];
__device__ __align__(16) float g_V[NN*CC];
__device__ __align__(16) float g_aggi[NN*CC];
__device__ __align__(16) float g_aggj[NN*CC];
__device__ __align__(16) float g_P  [NN*FF];
__device__ __align__(16) float g_x2 [NN*FF];
__device__ __align__(16) float g_x3 [NN*FF];
__device__ __align__(16) float g_e2 [NN*NN];
__device__ __align__(16) float g_e2T[NN*NN];
__device__ __align__(16) float g_aT [NN*NN];
__device__ __align__(16) float g_eT [NN*NN];

// ---------------- fused 400x400 transposes: z=0 -> a->aT, z=1 -> e->eT -------------
__global__ void transpose2_kernel(const float* __restrict__ a, float* __restrict__ aT,
                                  const float* __restrict__ e, float* __restrict__ eT)
{
    const float* src = blockIdx.z ? e : a;
    float*       dst = blockIdx.z ? eT : aT;
    __shared__ float tile[32][33];
    int x = blockIdx.x * 32 + threadIdx.x;
    int y = blockIdx.y * 32 + threadIdx.y;
#pragma unroll
    for (int dy = 0; dy < 32; dy += 8)
        if (x < NN && (y + dy) < NN)
            tile[threadIdx.y + dy][threadIdx.x] = src[(y + dy) * NN + x];
    __syncthreads();
    int x2 = blockIdx.y * 32 + threadIdx.x;
    int y2 = blockIdx.x * 32 + threadIdx.y;
#pragma unroll
    for (int dy = 0; dy < 32; dy += 8)
        if (x2 < NN && (y2 + dy) < NN)
            dst[(y2 + dy) * NN + x2] = tile[threadIdx.x][threadIdx.y + dy];
}

// ---------------- xw: [U | V | P] = x @ [swU | swV | nw[0:240]] ----------------
// grid 100 (4-row tiles), 304 threads (one output column each).
// cols 0-31 -> U (sw rows 0:240), 32-63 -> V (sw rows 240:480), 64-303 -> P (nw rows 0:240)
__global__ __launch_bounds__(304) void xw_kernel(
    const float* __restrict__ xsrc,
    const float* __restrict__ sw,
    const float* __restrict__ nwx,
    float* __restrict__ U, float* __restrict__ V, float* __restrict__ P)
{
    __shared__ __align__(16) float xs[4 * FF];
    int r0 = blockIdx.x * 4;
    for (int idx = threadIdx.x; idx < 4 * FF / 4; idx += 304) {
        int r = idx / 60, q = idx % 60;
        ((float4*)xs)[r * 60 + q] = ((const float4*)(xsrc + (r0 + r) * FF))[q];
    }
    __syncthreads();

    int j = threadIdx.x;
    const float* wp;
    int stride;
    if (j < 64) { wp = sw + (j < 32 ? j : 240 * CC + (j - 32)); stride = CC; }
    else        { wp = nwx + (j - 64);                          stride = FF; }

    float a0 = 0.f, a1 = 0.f, a2 = 0.f, a3 = 0.f;
#pragma unroll 4
    for (int k = 0; k < FF; k++) {
        float w = __ldg(wp); wp += stride;
        a0 = fmaf(xs[k],          w, a0);
        a1 = fmaf(xs[FF + k],     w, a1);
        a2 = fmaf(xs[2 * FF + k], w, a2);
        a3 = fmaf(xs[3 * FF + k], w, a3);
    }

    float* outp; int oc, ost;
    if (j < 32)      { outp = U; oc = j;      ost = CC; }
    else if (j < 64) { outp = V; oc = j - 32; ost = CC; }
    else             { outp = P; oc = j - 64; ost = FF; }
    outp[(r0 + 0) * ost + oc] = a0;
    outp[(r0 + 1) * ost + oc] = a1;
    outp[(r0 + 2) * ost + oc] = a2;
    outp[(r0 + 3) * ost + oc] = a3;
}

// ---------------- small: xout = P + [aggi|aggj] @ nwagg + nb  (K=64) ----------------
// grid 100 (4-row tiles), 240 threads (one feature each)
__global__ __launch_bounds__(240) void small_kernel(
    const float* __restrict__ P,
    const float* __restrict__ aggi,
    const float* __restrict__ aggj,
    const float* __restrict__ nwagg,   // (64, 240) = nw rows 240..303
    const float* __restrict__ nb,
    float* __restrict__ xout)
{
    __shared__ float ag[4 * 64];
    int r0 = blockIdx.x * 4;
    if (threadIdx.x < 128) {
        int r = threadIdx.x >> 5, c = threadIdx.x & 31;
        ag[r * 64 + c]      = aggi[(r0 + r) * CC + c];
        ag[r * 64 + 32 + c] = aggj[(r0 + r) * CC + c];
    }
    __syncthreads();

    int f = threadIdx.x;
    float b = nb[f];
    float a0 = P[(r0 + 0) * FF + f] + b;
    float a1 = P[(r0 + 1) * FF + f] + b;
    float a2 = P[(r0 + 2) * FF + f] + b;
    float a3 = P[(r0 + 3) * FF + f] + b;
#pragma unroll 4
    for (int k = 0; k < 64; k++) {
        float w = __ldg(&nwagg[k * FF + f]);
        a0 = fmaf(ag[k],       w, a0);
        a1 = fmaf(ag[64 + k],  w, a1);
        a2 = fmaf(ag[128 + k], w, a2);
        a3 = fmaf(ag[192 + k], w, a3);
    }
    xout[(r0 + 0) * FF + f] = a0;
    xout[(r0 + 1) * FF + f] = a1;
    xout[(r0 + 2) * FF + f] = a2;
    xout[(r0 + 3) * FF + f] = a3;
}

// ---------------- fused pair pass: grid (400, 2); y=0 -> agg_i (+e_out), y=1 -> agg_j
__global__ __launch_bounds__(128) void pair_both_kernel(
    const float*  __restrict__ U,
    const float*  __restrict__ V,
    const float*  __restrict__ e,
    const float*  __restrict__ eT,
    const float*  __restrict__ a,
    const float*  __restrict__ aT,
    const float*  __restrict__ we,
    const float*  __restrict__ wet,
    const float*  __restrict__ sb,
    const float*  __restrict__ aiw, const float* __restrict__ aib,
    const float*  __restrict__ ajw, const float* __restrict__ ajb,
    const float*  __restrict__ ew,  const float* __restrict__ eb,
    float* __restrict__ aggi, float* __restrict__ aggj,
    float* __restrict__ e_out, float* __restrict__ e_outT)
{
    __shared__ float4 cw4[CC];            // {own[c]+sb[c], we[c], wet[c], gw[c]}
    __shared__ float  cew[CC];
    __shared__ float  red[128 * (CC + 1)]; // padded: conflict-free
    __shared__ float  part[128];

    int b    = blockIdx.x;
    int side = blockIdx.y;
    int tid  = threadIdx.x;

    const float*  own  = side ? V : U;
    const float4* oth4 = (const float4*)(side ? U : V);
    const float*  eFrow = (side ? eT : e)  + b * NN;
    const float*  eRrow = (side ? e  : eT) + b * NN;
    const float*  arow  = (side ? aT : a)  + b * NN;
    const float*  gw = side ? ajw : aiw;
    const float*  gb = side ? ajb : aib;
    float* agg_out = side ? aggj : aggi;
    const bool write_e = (side == 0) && (e_out != nullptr);

    if (tid < CC) {
        int c = tid;
        cw4[c] = make_float4(own[b * CC + c] + sb[c], we[c], wet[c], gw[c]);
        cew[c] = write_e ? ew[c] : 0.f;
    }
    __syncthreads();

    float gbias = gb[0];
    float ebias = write_e ? eb[0] : 0.f;

    float agg[CC];
#pragma unroll
    for (int c = 0; c < CC; c++) agg[c] = 0.f;

    for (int t = tid; t < NN; t += 128) {
        float eij = __ldg(&eFrow[t]);
        float eji = __ldg(&eRrow[t]);
        float am  = __ldg(&arow[t]);
        float ai = 0.f, eo = 0.f;
        float s[CC];
#pragma unroll
        for (int c4 = 0; c4 < CC / 4; c4++) {
            float4 v = __ldg(&oth4[t * (CC / 4) + c4]);
            float vv[4] = {v.x, v.y, v.z, v.w};
#pragma unroll
            for (int u = 0; u < 4; u++) {
                int c = c4 * 4 + u;
                float4 w = cw4[c];
                float pre = w.x + vv[u];
                pre = fmaf(eij, w.y, pre);
                pre = fmaf(eji, w.z, pre);
                float sv = fmaxf(pre, 0.f) * am;
                s[c] = sv;
                ai = fmaf(sv, w.w, ai);
                eo = fmaf(sv, cew[c], eo);
            }
        }
        float att = 1.f / (1.f + __expf(-(ai + gbias)));
        if (write_e) {
            float ev = eo + ebias;
            e_out[b * NN + t] = ev;
            e_outT[t * NN + b] = ev;
        }
#pragma unroll
        for (int c = 0; c < CC; c++) agg[c] = fmaf(att, s[c], agg[c]);
    }

    // conflict-free two-phase reduction over 128 threads
#pragma unroll
    for (int c = 0; c < CC; c++) red[tid * (CC + 1) + c] = agg[c];
    __syncthreads();
    {
        int c = tid & 31;
        int g = tid >> 5;
        float sum = 0.f;
#pragma unroll
        for (int u = 0; u < 32; u++)
            sum += red[(g * 32 + u) * (CC + 1) + c];
        part[tid] = sum;
    }
    __syncthreads();
    if (tid < CC)
        agg_out[b * CC + tid] = (part[tid] + part[32 + tid]) + (part[64 + tid] + part[96 + tid]);
}

// ---------------- final dense: out = x @ dw + db  (400x240 @ 240x1440) ----------------
__global__ __launch_bounds__(288) void dense_kernel(
    const float* __restrict__ x,
    const float* __restrict__ dw,
    const float* __restrict__ db,
    float* __restrict__ out)
{
    __shared__ __align__(16) float xs[FF * 16];  // transposed: xs[k*16 + r]
    int r0 = blockIdx.x * 16;
    for (int idx = threadIdx.x; idx < FF * 16; idx += 288) {
        int k = idx >> 4, r = idx & 15;
        xs[idx] = x[(r0 + r) * FF + k];
    }
    __syncthreads();

    int col = blockIdx.y * 288 + threadIdx.x;
    float bias = db[col];
    float acc[16];
#pragma unroll
    for (int r = 0; r < 16; r++) acc[r] = bias;

    const float4* xs4 = (const float4*)xs;
    for (int k = 0; k < FF; k++) {
        float wf = __ldg(&dw[k * LL + col]);
        float4 a0 = xs4[k * 4 + 0];
        float4 a1 = xs4[k * 4 + 1];
        float4 a2 = xs4[k * 4 + 2];
        float4 a3 = xs4[k * 4 + 3];
        acc[ 0] = fmaf(a0.x, wf, acc[ 0]);
        acc[ 1] = fmaf(a0.y, wf, acc[ 1]);
        acc[ 2] = fmaf(a0.z, wf, acc[ 2]);
        acc[ 3] = fmaf(a0.w, wf, acc[ 3]);
        acc[ 4] = fmaf(a1.x, wf, acc[ 4]);
        acc[ 5] = fmaf(a1.y, wf, acc[ 5]);
        acc[ 6] = fmaf(a1.z, wf, acc[ 6]);
        acc[ 7] = fmaf(a1.w, wf, acc[ 7]);
        acc[ 8] = fmaf(a2.x, wf, acc[ 8]);
        acc[ 9] = fmaf(a2.y, wf, acc[ 9]);
        acc[10] = fmaf(a2.z, wf, acc[10]);
        acc[11] = fmaf(a2.w, wf, acc[11]);
        acc[12] = fmaf(a3.x, wf, acc[12]);
        acc[13] = fmaf(a3.y, wf, acc[13]);
        acc[14] = fmaf(a3.z, wf, acc[14]);
        acc[15] = fmaf(a3.w, wf, acc[15]);
    }
#pragma unroll
    for (int r = 0; r < 16; r++)
        out[(r0 + r) * LL + col] = acc[r];
}

// ---------------- launch ----------------
extern "C" void kernel_launch(void* const* d_in, const int* in_sizes, int n_in,
                              void* d_out, int out_size)
{
    const float* x      = (const float*)d_in[0];
    const float* a      = (const float*)d_in[1];
    const float* e      = (const float*)d_in[2];
    const float* c1_sw  = (const float*)d_in[3];
    const float* c1_sb  = (const float*)d_in[4];
    const float* c1_aiw = (const float*)d_in[5];
    const float* c1_aib = (const float*)d_in[6];
    const float* c1_ajw = (const float*)d_in[7];
    const float* c1_ajb = (const float*)d_in[8];
    const float* c1_nw  = (const float*)d_in[9];
    const float* c1_nb  = (const float*)d_in[10];
    const float* c1_ew  = (const float*)d_in[11];
    const float* c1_eb  = (const float*)d_in[12];
    const float* c2_sw  = (const float*)d_in[13];
    const float* c2_sb  = (const float*)d_in[14];
    const float* c2_aiw = (const float*)d_in[15];
    const float* c2_aib = (const float*)d_in[16];
    const float* c2_ajw = (const float*)d_in[17];
    const float* c2_ajb = (const float*)d_in[18];
    const float* c2_nw  = (const float*)d_in[19];
    const float* c2_nb  = (const float*)d_in[20];
    const float* c2_ew  = (const float*)d_in[21];
    const float* c2_eb  = (const float*)d_in[22];
    const float* dw     = (const float*)d_in[23];
    const float* db     = (const float*)d_in[24];
    float* out = (float*)d_out;

    float *pU, *pV, *pAi, *pAj, *pP, *pX2, *pX3, *pE2, *pE2T, *pAT, *pET;
    cudaGetSymbolAddress((void**)&pU,   g_U);
    cudaGetSymbolAddress((void**)&pV,   g_V);
    cudaGetSymbolAddress((void**)&pAi,  g_aggi);
    cudaGetSymbolAddress((void**)&pAj,  g_aggj);
    cudaGetSymbolAddress((void**)&pP,   g_P);
    cudaGetSymbolAddress((void**)&pX2,  g_x2);
    cudaGetSymbolAddress((void**)&pX3,  g_x3);
    cudaGetSymbolAddress((void**)&pE2,  g_e2);
    cudaGetSymbolAddress((void**)&pE2T, g_e2T);
    cudaGetSymbolAddress((void**)&pAT,  g_aT);
    cudaGetSymbolAddress((void**)&pET,  g_eT);

    transpose2_kernel<<<dim3(13, 13, 2), dim3(32, 8)>>>(a, pAT, e, pET);

    // ---- layer 1 ----
    xw_kernel<<<100, 304>>>(x, c1_sw, c1_nw, pU, pV, pP);
    pair_both_kernel<<<dim3(NN, 2), 128>>>(pU, pV, e, pET, a, pAT,
        c1_sw + 480 * CC, c1_sw + 481 * CC, c1_sb,
        c1_aiw, c1_aib, c1_ajw, c1_ajb, c1_ew, c1_eb,
        pAi, pAj, pE2, pE2T);
    small_kernel<<<100, 240>>>(pP, pAi, pAj, c1_nw + 240 * FF, c1_nb, pX2);

    // ---- layer 2 (e_out not needed downstream) ----
    xw_kernel<<<100, 304>>>(pX2, c2_sw, c2_nw, pU, pV, pP);
    pair_both_kernel<<<dim3(NN, 2), 128>>>(pU, pV, pE2, pE2T, a, pAT,
        c2_sw + 480 * CC, c2_sw + 481 * CC, c2_sb,
        c2_aiw, c2_aib, c2_ajw, c2_ajb, nullptr, nullptr,
        pAi, pAj, nullptr, nullptr);
    small_kernel<<<100, 240>>>(pP, pAi, pAj, c2_nw + 240 * FF, c2_nb, pX3);

    // ---- final dense ----
    dense_kernel<<<dim3(25, 5), 288>>>(pX3, dw, db, out);
}

// round 5
// speedup vs baseline: 1.2040x; 1.2040x over previous
#include <cuda_runtime.h>

#define NN  400
#define FF  240
#define CC  32
#define LL  1440

// ---------------- scratch (device globals; no allocation allowed) ----------------
__device__ __align__(16) float g_U[NN*CC];
__device__ __align__(16) float g_V[NN*CC];
__device__ __align__(16) float g_aggi[NN*CC];
__device__ __align__(16) float g_aggj[NN*CC];
__device__ __align__(16) float g_e2 [NN*NN];
__device__ __align__(16) float g_e2T[NN*NN];
__device__ __align__(16) float g_aT [NN*NN];
__device__ __align__(16) float g_eT [NN*NN];
__device__ __align__(16) float g_x2[NN*FF];
__device__ __align__(16) float g_x3[NN*FF];

// ---------------- fused 400x400 transposes: z=0 -> a->aT, z=1 -> e->eT -------------
__global__ void transpose2_kernel(const float* __restrict__ a, float* __restrict__ aT,
                                  const float* __restrict__ e, float* __restrict__ eT)
{
    const float* src = blockIdx.z ? e : a;
    float*       dst = blockIdx.z ? eT : aT;
    __shared__ float tile[32][33];
    int x = blockIdx.x * 32 + threadIdx.x;
    int y = blockIdx.y * 32 + threadIdx.y;
#pragma unroll
    for (int dy = 0; dy < 32; dy += 8)
        if (x < NN && (y + dy) < NN)
            tile[threadIdx.y + dy][threadIdx.x] = src[(y + dy) * NN + x];
    __syncthreads();
    int x2 = blockIdx.y * 32 + threadIdx.x;
    int y2 = blockIdx.x * 32 + threadIdx.y;
#pragma unroll
    for (int dy = 0; dy < 32; dy += 8)
        if (x2 < NN && (y2 + dy) < NN)
            dst[(y2 + dy) * NN + x2] = tile[threadIdx.x][threadIdx.y + dy];
}

// ---------------- U = x @ sw[0:240], V = x @ sw[240:480] ----------------
__global__ __launch_bounds__(64) void uv_kernel(
    const float* __restrict__ x, const float* __restrict__ sw,
    float* __restrict__ U, float* __restrict__ V)
{
    __shared__ __align__(16) float xs[FF];
    int row = blockIdx.x;
    if (threadIdx.x < FF / 4)
        ((float4*)xs)[threadIdx.x] = ((const float4*)(x + row * FF))[threadIdx.x];
    __syncthreads();

    int half = threadIdx.x >> 5;
    int c    = threadIdx.x & 31;
    const float* w = sw + half * FF * CC + c;

    float acc[8];
#pragma unroll
    for (int u = 0; u < 8; u++) acc[u] = 0.f;
#pragma unroll 3
    for (int k = 0; k < FF; k += 8) {
#pragma unroll
        for (int u = 0; u < 8; u++)
            acc[u] = fmaf(xs[k + u], __ldg(&w[(k + u) * CC]), acc[u]);
    }
    float* dst = half ? V : U;
    dst[row * CC + c] = ((acc[0] + acc[1]) + (acc[2] + acc[3])) +
                        ((acc[4] + acc[5]) + (acc[6] + acc[7]));
}

// ---------------- pair pass v2: 2 rows per block; grid (200, 2) ----------------
// side 0 -> agg_i (+e_out), side 1 -> agg_j. oth4[t] loads shared across both rows.
__global__ __launch_bounds__(128) void pair_both_kernel(
    const float*  __restrict__ U,
    const float*  __restrict__ V,
    const float*  __restrict__ e,
    const float*  __restrict__ eT,
    const float*  __restrict__ a,
    const float*  __restrict__ aT,
    const float*  __restrict__ we,
    const float*  __restrict__ wet,
    const float*  __restrict__ sb,
    const float*  __restrict__ aiw, const float* __restrict__ aib,
    const float*  __restrict__ ajw, const float* __restrict__ ajb,
    const float*  __restrict__ ew,  const float* __restrict__ eb,
    float* __restrict__ aggi, float* __restrict__ aggj,
    float* __restrict__ e_out, float* __restrict__ e_outT)
{
    __shared__ float4 cw4[2][CC];          // per b: {own[c]+sb[c], we[c], wet[c], gw[c]}
    __shared__ float  cew[CC];
    __shared__ float  red[128 * (CC + 1)]; // padded: conflict-free
    __shared__ float  part[128];

    int b0   = blockIdx.x * 2;
    int side = blockIdx.y;
    int tid  = threadIdx.x;

    const float*  own  = side ? V : U;
    const float4* oth4 = (const float4*)(side ? U : V);
    const float*  eF   = side ? eT : e;
    const float*  eR   = side ? e  : eT;
    const float*  am   = side ? aT : a;
    const float*  gw = side ? ajw : aiw;
    const float*  gb = side ? ajb : aib;
    float* agg_out = side ? aggj : aggi;
    const bool write_e = (side == 0) && (e_out != nullptr);

    if (tid < 2 * CC) {
        int p = tid >> 5, c = tid & 31;
        cw4[p][c] = make_float4(own[(b0 + p) * CC + c] + sb[c], we[c], wet[c], gw[c]);
        if (tid < CC) cew[tid] = write_e ? ew[tid] : 0.f;
    }
    __syncthreads();

    float gbias = gb[0];
    float ebias = write_e ? eb[0] : 0.f;

    float agg0[CC], agg1[CC];
#pragma unroll
    for (int c = 0; c < CC; c++) { agg0[c] = 0.f; agg1[c] = 0.f; }

    for (int t = tid; t < NN; t += 128) {
        float ef0 = __ldg(&eF[b0 * NN + t]);
        float er0 = __ldg(&eR[b0 * NN + t]);
        float am0 = __ldg(&am[b0 * NN + t]);
        float ef1 = __ldg(&eF[(b0 + 1) * NN + t]);
        float er1 = __ldg(&eR[(b0 + 1) * NN + t]);
        float am1 = __ldg(&am[(b0 + 1) * NN + t]);
        float v[CC];
#pragma unroll
        for (int c4 = 0; c4 < CC / 4; c4++) {
            float4 vv = __ldg(&oth4[t * (CC / 4) + c4]);
            v[c4 * 4 + 0] = vv.x; v[c4 * 4 + 1] = vv.y;
            v[c4 * 4 + 2] = vv.z; v[c4 * 4 + 3] = vv.w;
        }
        // ---- row b0 ----
        {
            float ai = 0.f, eo = 0.f;
            float s[CC];
#pragma unroll
            for (int c = 0; c < CC; c++) {
                float4 w = cw4[0][c];
                float pre = w.x + v[c];
                pre = fmaf(ef0, w.y, pre);
                pre = fmaf(er0, w.z, pre);
                float sv = fmaxf(pre, 0.f) * am0;
                s[c] = sv;
                ai = fmaf(sv, w.w, ai);
                eo = fmaf(sv, cew[c], eo);
            }
            float att = 1.f / (1.f + __expf(-(ai + gbias)));
            if (write_e) {
                float ev = eo + ebias;
                e_out[b0 * NN + t] = ev;
                e_outT[t * NN + b0] = ev;
            }
#pragma unroll
            for (int c = 0; c < CC; c++) agg0[c] = fmaf(att, s[c], agg0[c]);
        }
        // ---- row b0+1 ----
        {
            float ai = 0.f, eo = 0.f;
            float s[CC];
#pragma unroll
            for (int c = 0; c < CC; c++) {
                float4 w = cw4[1][c];
                float pre = w.x + v[c];
                pre = fmaf(ef1, w.y, pre);
                pre = fmaf(er1, w.z, pre);
                float sv = fmaxf(pre, 0.f) * am1;
                s[c] = sv;
                ai = fmaf(sv, w.w, ai);
                eo = fmaf(sv, cew[c], eo);
            }
            float att = 1.f / (1.f + __expf(-(ai + gbias)));
            if (write_e) {
                float ev = eo + ebias;
                e_out[(b0 + 1) * NN + t] = ev;
                e_outT[t * NN + b0 + 1] = ev;
            }
#pragma unroll
            for (int c = 0; c < CC; c++) agg1[c] = fmaf(att, s[c], agg1[c]);
        }
    }

    // conflict-free reductions, b0 then b0+1
#pragma unroll
    for (int c = 0; c < CC; c++) red[tid * (CC + 1) + c] = agg0[c];
    __syncthreads();
    {
        int c = tid & 31, g = tid >> 5;
        float sum = 0.f;
#pragma unroll
        for (int u = 0; u < 32; u++) sum += red[(g * 32 + u) * (CC + 1) + c];
        part[tid] = sum;
    }
    __syncthreads();
    if (tid < CC)
        agg_out[b0 * CC + tid] = (part[tid] + part[32 + tid]) + (part[64 + tid] + part[96 + tid]);
    __syncthreads();
#pragma unroll
    for (int c = 0; c < CC; c++) red[tid * (CC + 1) + c] = agg1[c];
    __syncthreads();
    {
        int c = tid & 31, g = tid >> 5;
        float sum = 0.f;
#pragma unroll
        for (int u = 0; u < 32; u++) sum += red[(g * 32 + u) * (CC + 1) + c];
        part[tid] = sum;
    }
    __syncthreads();
    if (tid < CC)
        agg_out[(b0 + 1) * CC + tid] = (part[tid] + part[32 + tid]) + (part[64 + tid] + part[96 + tid]);
}

// ---------------- node model v3: out = [x | agg_i | agg_j] @ nw + nb ----------------
// grid (100 row-tiles of 4, 2 col-halves of 120); 512 thr = 4 kq x 128 slots (120 active)
__global__ __launch_bounds__(512) void node_gemm_kernel(
    const float* __restrict__ x,
    const float* __restrict__ aggi,
    const float* __restrict__ aggj,
    const float* __restrict__ nw,
    const float* __restrict__ nb,
    float* __restrict__ out)
{
    const int K  = FF + 2 * CC;                 // 304
    const int KQ = K / 4;                       // 76
    __shared__ __align__(16) float cs[304 * 4]; // transposed: cs[k*4 + r]
    __shared__ float red[3 * 4 * 120];          // kq=1..3 partials

    int r0 = blockIdx.x * 4;
    int c0 = blockIdx.y * 120;
    for (int idx = threadIdx.x; idx < K * 4; idx += 512) {
        int k = idx >> 2, r = idx & 3;
        int row = r0 + r;
        float v;
        if (k < FF)            v = x[row * FF + k];
        else if (k < FF + CC)  v = aggi[row * CC + (k - FF)];
        else                   v = aggj[row * CC + (k - FF - CC)];
        cs[idx] = v;
    }
    __syncthreads();

    int kq = threadIdx.x >> 7;
    int c  = threadIdx.x & 127;
    bool active = (c < 120);
    int col = c0 + (c < 120 ? c : 119);
    int kbeg = kq * KQ;

    float a0 = 0.f, a1 = 0.f, a2 = 0.f, a3 = 0.f;
    const float4* cs4 = (const float4*)cs;
#pragma unroll 4
    for (int k = kbeg; k < kbeg + KQ; k++) {
        float wf = __ldg(&nw[k * FF + col]);
        float4 av = cs4[k];
        a0 = fmaf(av.x, wf, a0);
        a1 = fmaf(av.y, wf, a1);
        a2 = fmaf(av.z, wf, a2);
        a3 = fmaf(av.w, wf, a3);
    }
    if (active && kq > 0) {
        float* my = red + (kq - 1) * 480 + c;
        my[0]   = a0;
        my[120] = a1;
        my[240] = a2;
        my[360] = a3;
    }
    __syncthreads();
    if (active && kq == 0) {
        float bias = nb[col];
        const float* p = red + c;
        out[(r0 + 0) * FF + col] = a0 + bias + p[0]   + p[480]   + p[960];
        out[(r0 + 1) * FF + col] = a1 + bias + p[120] + p[600]   + p[1080];
        out[(r0 + 2) * FF + col] = a2 + bias + p[240] + p[720]   + p[1200];
        out[(r0 + 3) * FF + col] = a3 + bias + p[360] + p[840]   + p[1320];
    }
}

// ---------------- final dense: out = x @ dw + db  (400x240 @ 240x1440) ----------------
__global__ __launch_bounds__(288) void dense_kernel(
    const float* __restrict__ x,
    const float* __restrict__ dw,
    const float* __restrict__ db,
    float* __restrict__ out)
{
    __shared__ __align__(16) float xs[FF * 16];  // transposed: xs[k*16 + r]
    int r0 = blockIdx.x * 16;
    for (int idx = threadIdx.x; idx < FF * 16; idx += 288) {
        int k = idx >> 4, r = idx & 15;
        xs[idx] = x[(r0 + r) * FF + k];
    }
    __syncthreads();

    int col = blockIdx.y * 288 + threadIdx.x;
    float bias = db[col];
    float acc[16];
#pragma unroll
    for (int r = 0; r < 16; r++) acc[r] = bias;

    const float4* xs4 = (const float4*)xs;
#pragma unroll 8
    for (int k = 0; k < FF; k++) {
        float wf = __ldg(&dw[k * LL + col]);
        float4 a0 = xs4[k * 4 + 0];
        float4 a1 = xs4[k * 4 + 1];
        float4 a2 = xs4[k * 4 + 2];
        float4 a3 = xs4[k * 4 + 3];
        acc[ 0] = fmaf(a0.x, wf, acc[ 0]);
        acc[ 1] = fmaf(a0.y, wf, acc[ 1]);
        acc[ 2] = fmaf(a0.z, wf, acc[ 2]);
        acc[ 3] = fmaf(a0.w, wf, acc[ 3]);
        acc[ 4] = fmaf(a1.x, wf, acc[ 4]);
        acc[ 5] = fmaf(a1.y, wf, acc[ 5]);
        acc[ 6] = fmaf(a1.z, wf, acc[ 6]);
        acc[ 7] = fmaf(a1.w, wf, acc[ 7]);
        acc[ 8] = fmaf(a2.x, wf, acc[ 8]);
        acc[ 9] = fmaf(a2.y, wf, acc[ 9]);
        acc[10] = fmaf(a2.z, wf, acc[10]);
        acc[11] = fmaf(a2.w, wf, acc[11]);
        acc[12] = fmaf(a3.x, wf, acc[12]);
        acc[13] = fmaf(a3.y, wf, acc[13]);
        acc[14] = fmaf(a3.z, wf, acc[14]);
        acc[15] = fmaf(a3.w, wf, acc[15]);
    }
#pragma unroll
    for (int r = 0; r < 16; r++)
        out[(r0 + r) * LL + col] = acc[r];
}

// ---------------- launch ----------------
extern "C" void kernel_launch(void* const* d_in, const int* in_sizes, int n_in,
                              void* d_out, int out_size)
{
    const float* x      = (const float*)d_in[0];
    const float* a      = (const float*)d_in[1];
    const float* e      = (const float*)d_in[2];
    const float* c1_sw  = (const float*)d_in[3];
    const float* c1_sb  = (const float*)d_in[4];
    const float* c1_aiw = (const float*)d_in[5];
    const float* c1_aib = (const float*)d_in[6];
    const float* c1_ajw = (const float*)d_in[7];
    const float* c1_ajb = (const float*)d_in[8];
    const float* c1_nw  = (const float*)d_in[9];
    const float* c1_nb  = (const float*)d_in[10];
    const float* c1_ew  = (const float*)d_in[11];
    const float* c1_eb  = (const float*)d_in[12];
    const float* c2_sw  = (const float*)d_in[13];
    const float* c2_sb  = (const float*)d_in[14];
    const float* c2_aiw = (const float*)d_in[15];
    const float* c2_aib = (const float*)d_in[16];
    const float* c2_ajw = (const float*)d_in[17];
    const float* c2_ajb = (const float*)d_in[18];
    const float* c2_nw  = (const float*)d_in[19];
    const float* c2_nb  = (const float*)d_in[20];
    const float* c2_ew  = (const float*)d_in[21];
    const float* c2_eb  = (const float*)d_in[22];
    const float* dw     = (const float*)d_in[23];
    const float* db     = (const float*)d_in[24];
    float* out = (float*)d_out;

    float *pU, *pV, *pAi, *pAj, *pE2, *pE2T, *pAT, *pET, *pX2, *pX3;
    cudaGetSymbolAddress((void**)&pU,   g_U);
    cudaGetSymbolAddress((void**)&pV,   g_V);
    cudaGetSymbolAddress((void**)&pAi,  g_aggi);
    cudaGetSymbolAddress((void**)&pAj,  g_aggj);
    cudaGetSymbolAddress((void**)&pE2,  g_e2);
    cudaGetSymbolAddress((void**)&pE2T, g_e2T);
    cudaGetSymbolAddress((void**)&pAT,  g_aT);
    cudaGetSymbolAddress((void**)&pET,  g_eT);
    cudaGetSymbolAddress((void**)&pX2,  g_x2);
    cudaGetSymbolAddress((void**)&pX3,  g_x3);

    transpose2_kernel<<<dim3(13, 13, 2), dim3(32, 8)>>>(a, pAT, e, pET);

    // ---- layer 1 ----
    uv_kernel<<<NN, 64>>>(x, c1_sw, pU, pV);
    pair_both_kernel<<<dim3(NN / 2, 2), 128>>>(pU, pV, e, pET, a, pAT,
        c1_sw + 480 * CC, c1_sw + 481 * CC, c1_sb,
        c1_aiw, c1_aib, c1_ajw, c1_ajb, c1_ew, c1_eb,
        pAi, pAj, pE2, pE2T);
    node_gemm_kernel<<<dim3(100, 2), 512>>>(x, pAi, pAj, c1_nw, c1_nb, pX2);

    // ---- layer 2 (e_out not needed downstream) ----
    uv_kernel<<<NN, 64>>>(pX2, c2_sw, pU, pV);
    pair_both_kernel<<<dim3(NN / 2, 2), 128>>>(pU, pV, pE2, pE2T, a, pAT,
        c2_sw + 480 * CC, c2_sw + 481 * CC, c2_sb,
        c2_aiw, c2_aib, c2_ajw, c2_ajb, nullptr, nullptr,
        pAi, pAj, nullptr, nullptr);
    node_gemm_kernel<<<dim3(100, 2), 512>>>(pX2, pAi, pAj, c2_nw, c2_nb, pX3);

    // ---- final dense ----
    dense_kernel<<<dim3(25, 5), 288>>>(pX3, dw, db, out);
}